// round 1
// baseline (speedup 1.0000x reference)
#include <cuda_runtime.h>

#define B_SZ   128
#define NNODES 2047
#define LEAVES 1024
#define DIN    512
#define NL     64

// ---------------- device scratch (static; no allocations) ----------------
__device__ float g_emis[(size_t)B_SZ * NNODES * NL];   // 67 MB
__device__ float g_bufA[(size_t)B_SZ * 512 * NL];      // 16.8 MB (levels 9,7,5,3,1)
__device__ float g_bufB[(size_t)B_SZ * 256 * NL];      // 8.4 MB  (levels 8,6,4,2)
__device__ float g_expT[NL * NL];                      // exp(trans)

typedef unsigned long long u64;

__device__ __forceinline__ u64 fma2(u64 a, u64 b, u64 c) {
    u64 d; asm("fma.rn.f32x2 %0, %1, %2, %3;" : "=l"(d) : "l"(a), "l"(b), "l"(c)); return d;
}
__device__ __forceinline__ u64 splat2(float x) {
    u64 d; asm("mov.b64 %0, {%1, %1};" : "=l"(d) : "f"(x)); return d;
}
__device__ __forceinline__ float2 unpack2(u64 v) {
    float2 r; asm("mov.b64 {%0, %1}, %2;" : "=f"(r.x), "=f"(r.y) : "l"(v)); return r;
}

// ---------------- expT = exp(trans) ----------------
__global__ void expT_kernel(const float* __restrict__ trans) {
    int i = blockIdx.x * blockDim.x + threadIdx.x;
    if (i < NL * NL) g_expT[i] = expf(trans[i]);
}

// ---------------- emission GEMM: emis = hidden @ W + b ----------------
// block = 256 threads, 512 rows/block; thread owns rows (r0, r0+256), all 64 cols
// acc: 64 packed f32x2 (col pairs). W broadcast from smem via LDS.128.
#define GT 256
#define ROWS_PER_BLOCK 512

__global__ __launch_bounds__(GT) void gemm_kernel(
    const float* __restrict__ A, const float* __restrict__ W,
    const float* __restrict__ bias, float* __restrict__ out, int M)
{
    extern __shared__ float Wsm[];  // DIN*NL floats + NL bias
    {
        const float4* W4 = (const float4*)W;
        float4* S4 = (float4*)Wsm;
        for (int i = threadIdx.x; i < DIN * NL / 4; i += GT) S4[i] = W4[i];
        if (threadIdx.x < NL) Wsm[DIN * NL + threadIdx.x] = bias[threadIdx.x];
    }
    __syncthreads();

    int r0 = blockIdx.x * ROWS_PER_BLOCK + threadIdx.x;
    int r1 = r0 + GT;
    bool v1 = (r1 < M);
    const float* a0p = A + (size_t)r0 * DIN;
    const float* a1p = A + (size_t)(v1 ? r1 : r0) * DIN;  // clamp to stay in-bounds

    u64 acc0[32], acc1[32];
#pragma unroll
    for (int i = 0; i < 32; i++) { acc0[i] = 0ull; acc1[i] = 0ull; }

    for (int k = 0; k < DIN; k += 4) {
        float4 a0 = *(const float4*)(a0p + k);
        float4 a1 = *(const float4*)(a1p + k);
        float a0v[4] = {a0.x, a0.y, a0.z, a0.w};
        float a1v[4] = {a1.x, a1.y, a1.z, a1.w};
#pragma unroll
        for (int kk = 0; kk < 4; kk++) {
            u64 s0 = splat2(a0v[kk]);
            u64 s1 = splat2(a1v[kk]);
            const ulonglong2* wrow = (const ulonglong2*)(Wsm + (k + kk) * NL);
#pragma unroll
            for (int q = 0; q < 16; q++) {
                ulonglong2 wp = wrow[q];   // 4 cols: broadcast LDS.128
                acc0[2*q]   = fma2(s0, wp.x, acc0[2*q]);
                acc1[2*q]   = fma2(s1, wp.x, acc1[2*q]);
                acc0[2*q+1] = fma2(s0, wp.y, acc0[2*q+1]);
                acc1[2*q+1] = fma2(s1, wp.y, acc1[2*q+1]);
            }
        }
    }

    float* o0 = out + (size_t)r0 * NL;
    float* o1 = out + (size_t)r1 * NL;
#pragma unroll
    for (int cp = 0; cp < 32; cp++) {
        float2 bb = *(const float2*)&Wsm[DIN * NL + 2 * cp];
        float2 u0 = unpack2(acc0[cp]);
        u0.x += bb.x; u0.y += bb.y;
        *(float2*)(o0 + 2 * cp) = u0;
        if (v1) {
            float2 u1 = unpack2(acc1[cp]);
            u1.x += bb.x; u1.y += bb.y;
            *(float2*)(o1 + 2 * cp) = u1;
        }
    }
}

// ---------------- tree merge (one level) ----------------
// LSE_k(x_k + trans[l,k]) = m + log( sum_k exp(x_k - m) * expT[l,k] )
// block = 128 threads = 2 node-groups of 64; thread owns label l, expT row in regs.
__global__ __launch_bounds__(128) void merge_kernel(
    const float* __restrict__ prev, int prevStrideB,
    const float* __restrict__ emisLevel,    // g_emis + (n-1)*NL
    float* __restrict__ outp, int outStrideB,
    int n, int total)                       // total = B_SZ * n
{
    __shared__ float el[2][64];
    __shared__ float er[2][64];
    __shared__ float wmax[2][2][2];

    int tid = threadIdx.x;
    int g = tid >> 6, l = tid & 63;
    int lane = tid & 31, wig = (tid >> 5) & 1;

    u64 w2[32];
    const u64* wrow = (const u64*)(g_expT + l * 64);
#pragma unroll
    for (int q = 0; q < 32; q++) w2[q] = wrow[q];

    for (int base = blockIdx.x * 2; base < total; base += gridDim.x * 2) {
        int nodeIdx = base + g;
        bool active = nodeIdx < total;
        int node = active ? nodeIdx : 0;
        int b = node / n;
        int i = node - b * n;

        const float* lp = prev + (size_t)b * prevStrideB + (size_t)(2 * i) * NL;
        float lv = lp[l];
        float rv = lp[NL + l];

        float ml = lv, mr = rv;
#pragma unroll
        for (int off = 16; off; off >>= 1) {
            ml = fmaxf(ml, __shfl_xor_sync(0xffffffffu, ml, off));
            mr = fmaxf(mr, __shfl_xor_sync(0xffffffffu, mr, off));
        }
        if (lane == 0) { wmax[g][wig][0] = ml; wmax[g][wig][1] = mr; }
        __syncthreads();
        ml = fmaxf(wmax[g][0][0], wmax[g][1][0]);
        mr = fmaxf(wmax[g][0][1], wmax[g][1][1]);

        el[g][l] = __expf(lv - ml);
        er[g][l] = __expf(rv - mr);
        __syncthreads();

        u64 al0 = 0, al1 = 0, ar0 = 0, ar1 = 0;
        const ulonglong2* e2l = (const ulonglong2*)el[g];
        const ulonglong2* e2r = (const ulonglong2*)er[g];
#pragma unroll
        for (int q = 0; q < 16; q++) {
            ulonglong2 pl = e2l[q];   // broadcast LDS.128: k = 4q..4q+3
            ulonglong2 pr = e2r[q];
            al0 = fma2(w2[2*q],   pl.x, al0);
            ar0 = fma2(w2[2*q],   pr.x, ar0);
            al1 = fma2(w2[2*q+1], pl.y, al1);
            ar1 = fma2(w2[2*q+1], pr.y, ar1);
        }
        float2 fl0 = unpack2(al0), fl1 = unpack2(al1);
        float2 fr0 = unpack2(ar0), fr1 = unpack2(ar1);
        float accl = (fl0.x + fl0.y) + (fl1.x + fl1.y);
        float accr = (fr0.x + fr0.y) + (fr1.x + fr1.y);

        float res = emisLevel[(size_t)b * (NNODES * NL) + (size_t)i * NL + l]
                  + __logf(accl) + ml + __logf(accr) + mr;
        if (active)
            outp[(size_t)b * outStrideB + (size_t)i * NL + l] = res;
        __syncthreads();   // protect smem reuse
    }
}

// ---------------- launch ----------------
extern "C" void kernel_launch(void* const* d_in, const int* in_sizes, int n_in,
                              void* d_out, int out_size)
{
    const float* hidden = (const float*)d_in[0];
    const float* W      = (const float*)d_in[1];
    const float* bias   = (const float*)d_in[2];
    const float* trans  = (const float*)d_in[3];
    float* out = (float*)d_out;

    float *emis, *bufA, *bufB;
    cudaGetSymbolAddress((void**)&emis, g_emis);
    cudaGetSymbolAddress((void**)&bufA, g_bufA);
    cudaGetSymbolAddress((void**)&bufB, g_bufB);

    expT_kernel<<<(NL * NL + 255) / 256, 256>>>(trans);

    int M = B_SZ * NNODES;
    int smem = (DIN * NL + NL) * (int)sizeof(float);   // 128.25 KB
    cudaFuncSetAttribute(gemm_kernel, cudaFuncAttributeMaxDynamicSharedMemorySize, smem);
    gemm_kernel<<<(M + ROWS_PER_BLOCK - 1) / ROWS_PER_BLOCK, GT, smem>>>(hidden, W, bias, emis, M);

    const float* prev = emis + (LEAVES - 1) * NL;   // leaves
    int prevStride = NNODES * NL;
    for (int d = 9; d >= 0; --d) {
        int n = 1 << d;
        int total = B_SZ * n;
        float* o; int os;
        if (d == 0)                { o = out;  os = NL; }
        else if (((9 - d) & 1) == 0) { o = bufA; os = n * NL; }
        else                       { o = bufB; os = n * NL; }
        int blocks = (total + 1) / 2;
        if (blocks > 2048) blocks = 2048;
        merge_kernel<<<blocks, 128>>>(prev, prevStride, emis + (n - 1) * NL, o, os, n, total);
        prev = o; prevStride = os;
    }
}

// round 2
// speedup vs baseline: 1.5984x; 1.5984x over previous
#include <cuda_runtime.h>

#define B_SZ   128
#define NNODES 2047
#define LEAVES 1024
#define DIN    512
#define NL     64

typedef unsigned long long u64;

// ---------------- device scratch (static; no allocations) ----------------
__device__ float g_emis[(size_t)B_SZ * NNODES * NL];   // 67 MB
__device__ float g_bufA[(size_t)B_SZ * 512 * NL];      // odd levels
__device__ float g_bufB[(size_t)B_SZ * 256 * NL];      // even levels
__device__ u64   g_w2[32 * NL];                        // [kp][l] = {expT[l][2kp], expT[l][2kp+1]}

// ---------------- packed f32x2 helpers ----------------
__device__ __forceinline__ u64 fma2(u64 a, u64 b, u64 c) {
    u64 d; asm("fma.rn.f32x2 %0, %1, %2, %3;" : "=l"(d) : "l"(a), "l"(b), "l"(c)); return d;
}
__device__ __forceinline__ u64 splat2(float x) {
    u64 d; asm("mov.b64 %0, {%1, %1};" : "=l"(d) : "f"(x)); return d;
}
__device__ __forceinline__ u64 pack2(float lo, float hi) {
    u64 d; asm("mov.b64 %0, {%1, %2};" : "=l"(d) : "f"(lo), "f"(hi)); return d;
}
__device__ __forceinline__ float2 unpack2(u64 v) {
    float2 r; asm("mov.b64 {%0, %1}, %2;" : "=f"(r.x), "=f"(r.y) : "l"(v)); return r;
}

// ---------------- init: build k-pair-packed exp(trans) table ----------------
__global__ void init_kernel(const float* __restrict__ trans) {
    int i = blockIdx.x * blockDim.x + threadIdx.x;
    if (i < 32 * NL) {
        int kp = i >> 6, l = i & 63;
        float a = expf(trans[l * NL + 2 * kp]);
        float b = expf(trans[l * NL + 2 * kp + 1]);
        g_w2[kp * NL + l] = pack2(a, b);
    }
}

// ---------------- emission GEMM: emis = hidden @ W + b ----------------
// 256 threads; thread tile = 4 rows x 16 cols (acc = 32 u64).
// rt = t>>2 (0..63) -> rows r0+rt*4..+3 ; ct = t&3 -> cols ct*16..+15.
// W resident in smem as u64 col-pairs; A via LDG.128 double-buffered 8k ahead.
#define GEMM_SMEM_U64 (DIN * 32)   // 16384 u64 = 128KB

#define GEMM_COMPUTE(BUF, KB)                                              \
  {                                                                        \
    _Pragma("unroll")                                                      \
    for (int h = 0; h < 2; ++h) {                                          \
      _Pragma("unroll")                                                    \
      for (int kk = 0; kk < 4; ++kk) {                                     \
        int k = (KB) + h * 4 + kk;                                         \
        const u64* wrow = sm + k * 32 + ct * 8;                            \
        ulonglong2 wa = *(const ulonglong2*)(wrow);                        \
        ulonglong2 wb = *(const ulonglong2*)(wrow + 2);                    \
        ulonglong2 wc = *(const ulonglong2*)(wrow + 4);                    \
        ulonglong2 wd = *(const ulonglong2*)(wrow + 6);                    \
        _Pragma("unroll")                                                  \
        for (int i = 0; i < 4; ++i) {                                      \
          u64 s = splat2(((const float*)&BUF[i][h])[kk]);                  \
          acc[i][0] = fma2(s, wa.x, acc[i][0]);                            \
          acc[i][1] = fma2(s, wa.y, acc[i][1]);                            \
          acc[i][2] = fma2(s, wb.x, acc[i][2]);                            \
          acc[i][3] = fma2(s, wb.y, acc[i][3]);                            \
          acc[i][4] = fma2(s, wc.x, acc[i][4]);                            \
          acc[i][5] = fma2(s, wc.y, acc[i][5]);                            \
          acc[i][6] = fma2(s, wd.x, acc[i][6]);                            \
          acc[i][7] = fma2(s, wd.y, acc[i][7]);                            \
        }                                                                  \
      }                                                                    \
    }                                                                      \
  }

__global__ __launch_bounds__(256) void gemm_kernel(
    const float* __restrict__ A, const float* __restrict__ W,
    const float* __restrict__ bias, float* __restrict__ out, int M)
{
    extern __shared__ u64 sm[];                 // [DIN*32] u64 + bias floats
    float* bsm = (float*)(sm + GEMM_SMEM_U64);
    {
        const float4* w4 = (const float4*)W;
        float4* s4 = (float4*)sm;
        for (int i = threadIdx.x; i < DIN * NL / 4; i += 256) s4[i] = w4[i];
        if (threadIdx.x < NL) bsm[threadIdx.x] = bias[threadIdx.x];
    }
    __syncthreads();

    int t = threadIdx.x;
    int rt = t >> 2, ct = t & 3;
    long r0 = (long)blockIdx.x * 256 + rt * 4;

    const float4* ap[4];
#pragma unroll
    for (int i = 0; i < 4; ++i) {
        long r = r0 + i; if (r > M - 1) r = M - 1;
        ap[i] = (const float4*)(A + r * DIN);
    }

    u64 acc[4][8];
#pragma unroll
    for (int i = 0; i < 4; ++i)
#pragma unroll
        for (int j = 0; j < 8; ++j) acc[i][j] = 0ull;

    float4 bufX[4][2], bufY[4][2];
#pragma unroll
    for (int i = 0; i < 4; ++i) { bufX[i][0] = ap[i][0]; bufX[i][1] = ap[i][1]; }

#pragma unroll 1
    for (int k8 = 0; k8 < 64; k8 += 2) {
        // prefetch chunk k8+1
#pragma unroll
        for (int i = 0; i < 4; ++i) {
            bufY[i][0] = ap[i][(k8 + 1) * 2];
            bufY[i][1] = ap[i][(k8 + 1) * 2 + 1];
        }
        GEMM_COMPUTE(bufX, k8 * 8);
        if (k8 + 2 < 64) {
#pragma unroll
            for (int i = 0; i < 4; ++i) {
                bufX[i][0] = ap[i][(k8 + 2) * 2];
                bufX[i][1] = ap[i][(k8 + 2) * 2 + 1];
            }
        }
        GEMM_COMPUTE(bufY, (k8 + 1) * 8);
    }

#pragma unroll
    for (int i = 0; i < 4; ++i) {
        long r = r0 + i;
        if (r < M) {
            float* orow = out + r * NL + ct * 16;
#pragma unroll
            for (int g = 0; g < 4; ++g) {
                float2 p0 = unpack2(acc[i][2 * g]);
                float2 p1 = unpack2(acc[i][2 * g + 1]);
                int cb = ct * 16 + 4 * g;
                float4 v;
                v.x = p0.x + bsm[cb];     v.y = p0.y + bsm[cb + 1];
                v.z = p1.x + bsm[cb + 2]; v.w = p1.y + bsm[cb + 3];
                *(float4*)(orow + 4 * g) = v;
            }
        }
    }
}

// ---------------- fused tree kernel: one block per batch, all 10 levels ----------------
// Tile = 128 nodes (256 child vectors). 512 threads = 32 cv-groups x 16 label-groups.
// Phase1: 4 threads/cv load 64 vals, quad-max via shfl, exp, pack k-pairs into E2s.
// Phase2: thread (cvg,lg): cv = cvg+32i (i<8), l = lg+16j (j<4); acc packed over k-pairs.
//         Per kp: 8 e-loads (coalesced) + 4 w-loads (broadcast) + 32 fma2.
// Epilogue: horizontal add, log, L/R combine via shfl_xor(1); even lanes store.
#define E2_PITCH 257                    // u64 pitch per kp row (odd -> 2-way STS only)
#define TREE_SMEM_BYTES ((2048 + 32 * E2_PITCH) * 8 + 256 * 4)

__global__ __launch_bounds__(512) void tree_kernel(
    const float* __restrict__ emis, float* __restrict__ bufA,
    float* __restrict__ bufB, float* __restrict__ outg)
{
    extern __shared__ u64 smem[];
    u64* W2s = smem;                         // 2048 u64
    u64* E2s = smem + 2048;                  // 32 * 257 u64
    float* mbuf = (float*)(smem + 2048 + 32 * E2_PITCH);   // 256 floats

    int t = threadIdx.x;
    int b = blockIdx.x;

    for (int i = t; i < 2048; i += 512) W2s[i] = g_w2[i];
    for (int i = t; i < 32 * E2_PITCH; i += 512) E2s[i] = 0ull;
    if (t < 256) mbuf[t] = 0.f;
    __syncthreads();

    const float* emisb = emis + (size_t)b * NNODES * NL;
    const float* prev  = emisb + (size_t)(LEAVES - 1) * NL;   // leaves
    float* bufAb = bufA + (size_t)b * 512 * NL;
    float* bufBb = bufB + (size_t)b * 256 * NL;

    int cvg = t & 31, lg = t >> 5;
    int sub = t & 3,  cquad = t >> 2;

    for (int d = 9; d >= 0; --d) {
        int n = 1 << d;
        const float* emisLvl = emisb + (size_t)(n - 1) * NL;
        float* outLvl = (d == 0) ? (outg + (size_t)b * NL)
                                 : ((d & 1) ? bufAb : bufBb);
        int ntiles = (n + 127) >> 7;
        for (int tile = 0; tile < ntiles; ++tile) {
            int i0 = tile << 7;
            int NT = n - i0; if (NT > 128) NT = 128;
            int ncv = 2 * NT;

            // ---- phase 1: load children, per-cv max, exp, pack k-pairs ----
#pragma unroll
            for (int co = 0; co < 256; co += 128) {
                int c = co + cquad;
                bool valid = c < ncv;
                int cc = valid ? c : 0;
                const float* src = prev + (size_t)(i0 * 2 + cc) * NL + sub * 16;
                float4 v0 = *(const float4*)(src);
                float4 v1 = *(const float4*)(src + 4);
                float4 v2 = *(const float4*)(src + 8);
                float4 v3 = *(const float4*)(src + 12);
                float vv[16] = {v0.x, v0.y, v0.z, v0.w, v1.x, v1.y, v1.z, v1.w,
                                v2.x, v2.y, v2.z, v2.w, v3.x, v3.y, v3.z, v3.w};
                float m = vv[0];
#pragma unroll
                for (int j = 1; j < 16; ++j) m = fmaxf(m, vv[j]);
                m = fmaxf(m, __shfl_xor_sync(0xffffffffu, m, 1));
                m = fmaxf(m, __shfl_xor_sync(0xffffffffu, m, 2));
                if (valid) {
#pragma unroll
                    for (int j = 0; j < 8; ++j) {
                        float e0 = __expf(vv[2 * j] - m);
                        float e1 = __expf(vv[2 * j + 1] - m);
                        E2s[(sub * 8 + j) * E2_PITCH + c] = pack2(e0, e1);
                    }
                    if (sub == 0) mbuf[c] = m;
                }
            }
            __syncthreads();

            // ---- phase 2: k-pair-packed matvec, 8 cv x 4 labels per thread ----
            u64 acc[8][4];
#pragma unroll
            for (int i = 0; i < 8; ++i)
#pragma unroll
                for (int j = 0; j < 4; ++j) acc[i][j] = 0ull;

#pragma unroll 2
            for (int kp = 0; kp < 32; ++kp) {
                const u64* er = E2s + kp * E2_PITCH + cvg;
                const u64* wr = W2s + kp * NL + lg;
                u64 w0 = wr[0], w1 = wr[16], w2v = wr[32], w3 = wr[48];
#pragma unroll
                for (int i = 0; i < 8; ++i) {
                    u64 e = er[32 * i];
                    acc[i][0] = fma2(e, w0,  acc[i][0]);
                    acc[i][1] = fma2(e, w1,  acc[i][1]);
                    acc[i][2] = fma2(e, w2v, acc[i][2]);
                    acc[i][3] = fma2(e, w3,  acc[i][3]);
                }
            }

            // ---- epilogue: hadd, log, combine L/R via lane^1, store ----
            bool isLeft = (cvg & 1) == 0;
#pragma unroll
            for (int i = 0; i < 8; ++i) {
                int cv = cvg + 32 * i;
                float mv = mbuf[cv];
#pragma unroll
                for (int j = 0; j < 4; ++j) {
                    float2 u = unpack2(acc[i][j]);
                    float lse = __logf(u.x + u.y) + mv;
                    float oth = __shfl_xor_sync(0xffffffffu, lse, 1);
                    if (isLeft && cv < ncv) {
                        int node = i0 + (cv >> 1);
                        int l = lg + 16 * j;
                        outLvl[(size_t)node * NL + l] =
                            emisLvl[(size_t)node * NL + l] + lse + oth;
                    }
                }
            }
            __syncthreads();
        }
        prev = outLvl;
    }
}

// ---------------- launch ----------------
extern "C" void kernel_launch(void* const* d_in, const int* in_sizes, int n_in,
                              void* d_out, int out_size)
{
    const float* hidden = (const float*)d_in[0];
    const float* W      = (const float*)d_in[1];
    const float* bias   = (const float*)d_in[2];
    const float* trans  = (const float*)d_in[3];
    float* out = (float*)d_out;

    float *emis, *bufA, *bufB;
    cudaGetSymbolAddress((void**)&emis, g_emis);
    cudaGetSymbolAddress((void**)&bufA, g_bufA);
    cudaGetSymbolAddress((void**)&bufB, g_bufB);

    init_kernel<<<8, 256>>>(trans);

    int M = B_SZ * NNODES;
    int gsmem = GEMM_SMEM_U64 * 8 + NL * 4;          // 128KB + bias
    cudaFuncSetAttribute(gemm_kernel, cudaFuncAttributeMaxDynamicSharedMemorySize, gsmem);
    gemm_kernel<<<(M + 255) / 256, 256, gsmem>>>(hidden, W, bias, emis, M);

    cudaFuncSetAttribute(tree_kernel, cudaFuncAttributeMaxDynamicSharedMemorySize, TREE_SMEM_BYTES);
    tree_kernel<<<B_SZ, 512, TREE_SMEM_BYTES>>>(emis, bufA, bufB, out);
}

// round 5
// speedup vs baseline: 3.5255x; 2.2056x over previous
#include <cuda_runtime.h>
#include <cuda_bf16.h>
#include <cstdint>

#define B_SZ   128
#define NNODES 2047
#define LEAVES 1024
#define DIN    512
#define NL     64
#define MROWS  (B_SZ * NNODES)          // 262016

typedef unsigned long long u64;

// ---------------- device scratch (static; no allocations) ----------------
__device__ float g_emis[(size_t)B_SZ * NNODES * NL];   // 67 MB
__device__ float g_bufA[(size_t)B_SZ * 512 * NL];      // odd levels
__device__ float g_bufB[(size_t)B_SZ * 256 * NL];      // even levels
__device__ u64   g_w2[32 * NL];                        // [kp][l] packed exp(trans)
__device__ uint4 g_Wfrag[32 * 8 * 32];                 // [kstep][ntile][lane] {bhi0,bhi1,blo0,blo1}

// ---------------- packed helpers ----------------
__device__ __forceinline__ u64 fma2(u64 a, u64 b, u64 c) {
    u64 d; asm("fma.rn.f32x2 %0, %1, %2, %3;" : "=l"(d) : "l"(a), "l"(b), "l"(c)); return d;
}
__device__ __forceinline__ u64 pack2(float lo, float hi) {
    u64 d; asm("mov.b64 %0, {%1, %2};" : "=l"(d) : "f"(lo), "f"(hi)); return d;
}
__device__ __forceinline__ float2 unpack2(u64 v) {
    float2 r; asm("mov.b64 {%0, %1}, %2;" : "=f"(r.x), "=f"(r.y) : "l"(v)); return r;
}
// bf16x2 hi/lo split: low half = x0 (even k), high half = x1 (odd k)
__device__ __forceinline__ void cvt_hilo(float x0, float x1, uint32_t& h, uint32_t& l) {
    asm("cvt.rn.satfinite.bf16x2.f32 %0, %1, %2;" : "=r"(h) : "f"(x1), "f"(x0));
    float r0 = x0 - __uint_as_float(h << 16);
    float r1 = x1 - __uint_as_float(h & 0xffff0000u);
    asm("cvt.rn.satfinite.bf16x2.f32 %0, %1, %2;" : "=r"(l) : "f"(r1), "f"(r0));
}
__device__ __forceinline__ void mma16816(float& d0, float& d1, float& d2, float& d3,
                                         uint32_t a0, uint32_t a1, uint32_t a2, uint32_t a3,
                                         uint32_t b0, uint32_t b1) {
    asm("mma.sync.aligned.m16n8k16.row.col.f32.bf16.bf16.f32 "
        "{%0,%1,%2,%3}, {%4,%5,%6,%7}, {%8,%9}, {%0,%1,%2,%3};"
        : "+f"(d0), "+f"(d1), "+f"(d2), "+f"(d3)
        : "r"(a0), "r"(a1), "r"(a2), "r"(a3), "r"(b0), "r"(b1));
}

// ---------------- init: exp(trans) pairs + W b-fragments (hi/lo) ----------------
__global__ void init_kernel(const float* __restrict__ trans, const float* __restrict__ W) {
    int i = blockIdx.x * blockDim.x + threadIdx.x;
    if (i < 2048) {
        int kp = i >> 6, l = i & 63;
        float a = expf(trans[l * NL + 2 * kp]);
        float b = expf(trans[l * NL + 2 * kp + 1]);
        g_w2[kp * NL + l] = pack2(a, b);
    }
    int j = i - 2048;
    if (j >= 0 && j < 32 * 8 * 32) {
        int lane = j & 31, t = (j >> 5) & 7, s = j >> 8;
        int n  = t * 8 + (lane >> 2);
        int k0 = s * 16 + (lane & 3) * 2;
        float w00 = W[k0 * NL + n],       w01 = W[(k0 + 1) * NL + n];
        float w10 = W[(k0 + 8) * NL + n], w11 = W[(k0 + 9) * NL + n];
        uint32_t bh0, bl0, bh1, bl1;
        cvt_hilo(w00, w01, bh0, bl0);
        cvt_hilo(w10, w11, bh1, bl1);
        g_Wfrag[j] = make_uint4(bh0, bh1, bl0, bl1);
    }
}

// ---------------- HMMA emission GEMM: emis = hidden @ W + b ----------------
// CTA = 256 rows, 8 warps x 32 rows (2 m16 tiles). smem: Wfrag 128KB + bias.
#define GS_TOTAL (131072 + 256)

extern __shared__ char dynsm[];

__global__ __launch_bounds__(256) void gemm_kernel(
    const float* __restrict__ A, const float* __restrict__ bias,
    float* __restrict__ out)
{
    uint4* Wsm = (uint4*)dynsm;
    float* bsm = (float*)(dynsm + 131072);
    int tid = threadIdx.x;
    {
        const uint4* src = g_Wfrag;
        for (int i = tid; i < 8192; i += 256) Wsm[i] = src[i];
        if (tid < NL) bsm[tid] = bias[tid];
    }
    __syncthreads();

    int lane = tid & 31, w = tid >> 5;
    long rowbase = (long)blockIdx.x * 256 + w * 32;
    int qr = lane >> 2;            // 0..7
    int qk = (lane & 3) * 2;       // 0,2,4,6

    // 4 row pointers: [rt*2 + rh] -> row rowbase + rt*16 + rh*8 + qr (clamped)
    const float* aptr[4];
#pragma unroll
    for (int rt = 0; rt < 2; ++rt)
#pragma unroll
        for (int rh = 0; rh < 2; ++rh) {
            long r = rowbase + rt * 16 + rh * 8 + qr;
            if (r > MROWS - 1) r = MROWS - 1;
            aptr[rt * 2 + rh] = A + r * DIN + qk;
        }

    float acc[2][8][4];
#pragma unroll
    for (int rt = 0; rt < 2; ++rt)
#pragma unroll
        for (int t = 0; t < 8; ++t)
#pragma unroll
            for (int e = 0; e < 4; ++e) acc[rt][t][e] = 0.f;

    float2 cur[4][2], nxt[4][2];
#pragma unroll
    for (int p = 0; p < 4; ++p) {
        cur[p][0] = *(const float2*)(aptr[p]);
        cur[p][1] = *(const float2*)(aptr[p] + 8);
    }

#pragma unroll 1
    for (int s = 0; s < 32; ++s) {
        if (s < 31) {
#pragma unroll
            for (int p = 0; p < 4; ++p) {
                nxt[p][0] = *(const float2*)(aptr[p] + (s + 1) * 16);
                nxt[p][1] = *(const float2*)(aptr[p] + (s + 1) * 16 + 8);
            }
        }
        // convert A fragments (hi + lo)
        uint32_t ah[2][4], al[2][4];
#pragma unroll
        for (int rt = 0; rt < 2; ++rt) {
            cvt_hilo(cur[2*rt][0].x,   cur[2*rt][0].y,   ah[rt][0], al[rt][0]);
            cvt_hilo(cur[2*rt+1][0].x, cur[2*rt+1][0].y, ah[rt][1], al[rt][1]);
            cvt_hilo(cur[2*rt][1].x,   cur[2*rt][1].y,   ah[rt][2], al[rt][2]);
            cvt_hilo(cur[2*rt+1][1].x, cur[2*rt+1][1].y, ah[rt][3], al[rt][3]);
        }
        // B fragments from smem + 3-product MMA
#pragma unroll
        for (int t = 0; t < 8; ++t) {
            uint4 wb = Wsm[(s * 8 + t) * 32 + lane];
#pragma unroll
            for (int rt = 0; rt < 2; ++rt) {
                mma16816(acc[rt][t][0], acc[rt][t][1], acc[rt][t][2], acc[rt][t][3],
                         ah[rt][0], ah[rt][1], ah[rt][2], ah[rt][3], wb.x, wb.y);  // hi*hi
                mma16816(acc[rt][t][0], acc[rt][t][1], acc[rt][t][2], acc[rt][t][3],
                         ah[rt][0], ah[rt][1], ah[rt][2], ah[rt][3], wb.z, wb.w);  // hi*lo
                mma16816(acc[rt][t][0], acc[rt][t][1], acc[rt][t][2], acc[rt][t][3],
                         al[rt][0], al[rt][1], al[rt][2], al[rt][3], wb.x, wb.y);  // lo*hi
            }
        }
#pragma unroll
        for (int p = 0; p < 4; ++p) { cur[p][0] = nxt[p][0]; cur[p][1] = nxt[p][1]; }
    }

    // epilogue: bias + store
#pragma unroll
    for (int rt = 0; rt < 2; ++rt)
#pragma unroll
        for (int rh = 0; rh < 2; ++rh) {
            long r = rowbase + rt * 16 + rh * 8 + qr;
            if (r < MROWS) {
                float* orow = out + r * NL;
#pragma unroll
                for (int t = 0; t < 8; ++t) {
                    int c = t * 8 + qk;
                    float2 v;
                    v.x = acc[rt][t][rh * 2 + 0] + bsm[c];
                    v.y = acc[rt][t][rh * 2 + 1] + bsm[c + 1];
                    *(float2*)(orow + c) = v;
                }
            }
        }
}

// ---------------- fused tree kernel (unchanged; near fma floor) ----------------
#define E2_PITCH 257
#define TREE_SMEM_BYTES ((2048 + 32 * E2_PITCH) * 8 + 256 * 4)

__global__ __launch_bounds__(512) void tree_kernel(
    const float* __restrict__ emis, float* __restrict__ bufA,
    float* __restrict__ bufB, float* __restrict__ outg)
{
    u64* smem = (u64*)dynsm;
    u64* W2s = smem;
    u64* E2s = smem + 2048;
    float* mbuf = (float*)(smem + 2048 + 32 * E2_PITCH);

    int t = threadIdx.x;
    int b = blockIdx.x;

    for (int i = t; i < 2048; i += 512) W2s[i] = g_w2[i];
    for (int i = t; i < 32 * E2_PITCH; i += 512) E2s[i] = 0ull;
    if (t < 256) mbuf[t] = 0.f;
    __syncthreads();

    const float* emisb = emis + (size_t)b * NNODES * NL;
    const float* prev  = emisb + (size_t)(LEAVES - 1) * NL;
    float* bufAb = bufA + (size_t)b * 512 * NL;
    float* bufBb = bufB + (size_t)b * 256 * NL;

    int cvg = t & 31, lg = t >> 5;
    int sub = t & 3,  cquad = t >> 2;

    for (int d = 9; d >= 0; --d) {
        int n = 1 << d;
        const float* emisLvl = emisb + (size_t)(n - 1) * NL;
        float* outLvl = (d == 0) ? (outg + (size_t)b * NL)
                                 : ((d & 1) ? bufAb : bufBb);
        int ntiles = (n + 127) >> 7;
        for (int tile = 0; tile < ntiles; ++tile) {
            int i0 = tile << 7;
            int NT = n - i0; if (NT > 128) NT = 128;
            int ncv = 2 * NT;

#pragma unroll
            for (int co = 0; co < 256; co += 128) {
                int c = co + cquad;
                bool valid = c < ncv;
                int cc = valid ? c : 0;
                const float* src = prev + (size_t)(i0 * 2 + cc) * NL + sub * 16;
                float4 v0 = *(const float4*)(src);
                float4 v1 = *(const float4*)(src + 4);
                float4 v2 = *(const float4*)(src + 8);
                float4 v3 = *(const float4*)(src + 12);
                float vv[16] = {v0.x, v0.y, v0.z, v0.w, v1.x, v1.y, v1.z, v1.w,
                                v2.x, v2.y, v2.z, v2.w, v3.x, v3.y, v3.z, v3.w};
                float m = vv[0];
#pragma unroll
                for (int j = 1; j < 16; ++j) m = fmaxf(m, vv[j]);
                m = fmaxf(m, __shfl_xor_sync(0xffffffffu, m, 1));
                m = fmaxf(m, __shfl_xor_sync(0xffffffffu, m, 2));
                if (valid) {
#pragma unroll
                    for (int j = 0; j < 8; ++j) {
                        float e0 = __expf(vv[2 * j] - m);
                        float e1 = __expf(vv[2 * j + 1] - m);
                        E2s[(sub * 8 + j) * E2_PITCH + c] = pack2(e0, e1);
                    }
                    if (sub == 0) mbuf[c] = m;
                }
            }
            __syncthreads();

            u64 acc[8][4];
#pragma unroll
            for (int i = 0; i < 8; ++i)
#pragma unroll
                for (int j = 0; j < 4; ++j) acc[i][j] = 0ull;

#pragma unroll 2
            for (int kp = 0; kp < 32; ++kp) {
                const u64* er = E2s + kp * E2_PITCH + cvg;
                const u64* wr = W2s + kp * NL + lg;
                u64 w0 = wr[0], w1 = wr[16], w2v = wr[32], w3 = wr[48];
#pragma unroll
                for (int i = 0; i < 8; ++i) {
                    u64 e = er[32 * i];
                    acc[i][0] = fma2(e, w0,  acc[i][0]);
                    acc[i][1] = fma2(e, w1,  acc[i][1]);
                    acc[i][2] = fma2(e, w2v, acc[i][2]);
                    acc[i][3] = fma2(e, w3,  acc[i][3]);
                }
            }

            bool isLeft = (cvg & 1) == 0;
#pragma unroll
            for (int i = 0; i < 8; ++i) {
                int cv = cvg + 32 * i;
                float mv = mbuf[cv];
#pragma unroll
                for (int j = 0; j < 4; ++j) {
                    float2 u = unpack2(acc[i][j]);
                    float lse = __logf(u.x + u.y) + mv;
                    float oth = __shfl_xor_sync(0xffffffffu, lse, 1);
                    if (isLeft && cv < ncv) {
                        int node = i0 + (cv >> 1);
                        int l = lg + 16 * j;
                        outLvl[(size_t)node * NL + l] =
                            emisLvl[(size_t)node * NL + l] + lse + oth;
                    }
                }
            }
            __syncthreads();
        }
        prev = outLvl;
    }
}

// ---------------- launch ----------------
extern "C" void kernel_launch(void* const* d_in, const int* in_sizes, int n_in,
                              void* d_out, int out_size)
{
    const float* hidden = (const float*)d_in[0];
    const float* W      = (const float*)d_in[1];
    const float* bias   = (const float*)d_in[2];
    const float* trans  = (const float*)d_in[3];
    float* out = (float*)d_out;

    float *emis, *bufA, *bufB;
    cudaGetSymbolAddress((void**)&emis, g_emis);
    cudaGetSymbolAddress((void**)&bufA, g_bufA);
    cudaGetSymbolAddress((void**)&bufB, g_bufB);

    init_kernel<<<(2048 + 32 * 8 * 32 + 255) / 256, 256>>>(trans, W);

    cudaFuncSetAttribute(gemm_kernel, cudaFuncAttributeMaxDynamicSharedMemorySize, GS_TOTAL);
    gemm_kernel<<<(MROWS + 255) / 256, 256, GS_TOTAL>>>(hidden, bias, emis);

    cudaFuncSetAttribute(tree_kernel, cudaFuncAttributeMaxDynamicSharedMemorySize, TREE_SMEM_BYTES);
    tree_kernel<<<B_SZ, 512, TREE_SMEM_BYTES>>>(emis, bufA, bufB, out);
}

// round 6
// speedup vs baseline: 3.6094x; 1.0238x over previous
#include <cuda_runtime.h>
#include <cuda_bf16.h>
#include <cstdint>

#define B_SZ   128
#define NNODES 2047
#define LEAVES 1024
#define DIN    512
#define NL     64
#define MROWS  (B_SZ * NNODES)          // 262016

typedef unsigned long long u64;

// ---------------- device scratch (static; no allocations) ----------------
__device__ float g_emis[(size_t)B_SZ * NNODES * NL];   // 67 MB
__device__ float g_bufA[(size_t)B_SZ * 512 * NL];      // odd levels
__device__ float g_bufB[(size_t)B_SZ * 256 * NL];      // even levels
__device__ u64   g_w2[32 * NL];                        // [kp][l] packed exp(trans)
__device__ uint4 g_Wfrag[32 * 8 * 32];                 // [kstep][ntile][lane] {bhi0,bhi1,blo0,blo1}

// ---------------- packed helpers ----------------
__device__ __forceinline__ u64 fma2(u64 a, u64 b, u64 c) {
    u64 d; asm("fma.rn.f32x2 %0, %1, %2, %3;" : "=l"(d) : "l"(a), "l"(b), "l"(c)); return d;
}
__device__ __forceinline__ u64 pack2(float lo, float hi) {
    u64 d; asm("mov.b64 %0, {%1, %2};" : "=l"(d) : "f"(lo), "f"(hi)); return d;
}
__device__ __forceinline__ float2 unpack2(u64 v) {
    float2 r; asm("mov.b64 {%0, %1}, %2;" : "=f"(r.x), "=f"(r.y) : "l"(v)); return r;
}
// bf16x2 hi/lo split: low half = x0 (even k), high half = x1 (odd k)
__device__ __forceinline__ void cvt_hilo(float x0, float x1, uint32_t& h, uint32_t& l) {
    asm("cvt.rn.satfinite.bf16x2.f32 %0, %1, %2;" : "=r"(h) : "f"(x1), "f"(x0));
    float r0 = x0 - __uint_as_float(h << 16);
    float r1 = x1 - __uint_as_float(h & 0xffff0000u);
    asm("cvt.rn.satfinite.bf16x2.f32 %0, %1, %2;" : "=r"(l) : "f"(r1), "f"(r0));
}
__device__ __forceinline__ void mma16816(float& d0, float& d1, float& d2, float& d3,
                                         uint32_t a0, uint32_t a1, uint32_t a2, uint32_t a3,
                                         uint32_t b0, uint32_t b1) {
    asm("mma.sync.aligned.m16n8k16.row.col.f32.bf16.bf16.f32 "
        "{%0,%1,%2,%3}, {%4,%5,%6,%7}, {%8,%9}, {%0,%1,%2,%3};"
        : "+f"(d0), "+f"(d1), "+f"(d2), "+f"(d3)
        : "r"(a0), "r"(a1), "r"(a2), "r"(a3), "r"(b0), "r"(b1));
}

// ---------------- init: exp(trans) pairs + W b-fragments (hi/lo) ----------------
__global__ void init_kernel(const float* __restrict__ trans, const float* __restrict__ W) {
    int i = blockIdx.x * blockDim.x + threadIdx.x;
    if (i < 2048) {
        int kp = i >> 6, l = i & 63;
        float a = expf(trans[l * NL + 2 * kp]);
        float b = expf(trans[l * NL + 2 * kp + 1]);
        g_w2[kp * NL + l] = pack2(a, b);
    }
    int j = i - 2048;
    if (j >= 0 && j < 32 * 8 * 32) {
        int lane = j & 31, t = (j >> 5) & 7, s = j >> 8;
        int n  = t * 8 + (lane >> 2);
        int k0 = s * 16 + (lane & 3) * 2;
        float w00 = W[k0 * NL + n],       w01 = W[(k0 + 1) * NL + n];
        float w10 = W[(k0 + 8) * NL + n], w11 = W[(k0 + 9) * NL + n];
        uint32_t bh0, bl0, bh1, bl1;
        cvt_hilo(w00, w01, bh0, bl0);
        cvt_hilo(w10, w11, bh1, bl1);
        g_Wfrag[j] = make_uint4(bh0, bh1, bl0, bl1);
    }
}

// ---------------- HMMA emission GEMM: emis = hidden @ W + b ----------------
// CTA = 512 rows, 16 warps x 32 rows (2 m16 tiles). smem: Wfrag 128KB + bias.
#define GS_TOTAL (131072 + 256)

extern __shared__ char dynsm[];

__global__ __launch_bounds__(512) void gemm_kernel(
    const float* __restrict__ A, const float* __restrict__ bias,
    float* __restrict__ out)
{
    uint4* Wsm = (uint4*)dynsm;
    float* bsm = (float*)(dynsm + 131072);
    int tid = threadIdx.x;
    {
        const uint4* src = g_Wfrag;
        for (int i = tid; i < 8192; i += 512) Wsm[i] = src[i];
        if (tid < NL) bsm[tid] = bias[tid];
    }
    __syncthreads();

    int lane = tid & 31, w = tid >> 5;
    long rowbase = (long)blockIdx.x * 512 + w * 32;
    int qr = lane >> 2;            // 0..7
    int qk = (lane & 3) * 2;       // 0,2,4,6

    // 4 row pointers: [rt*2 + rh] -> row rowbase + rt*16 + rh*8 + qr (clamped)
    const float* aptr[4];
#pragma unroll
    for (int rt = 0; rt < 2; ++rt)
#pragma unroll
        for (int rh = 0; rh < 2; ++rh) {
            long r = rowbase + rt * 16 + rh * 8 + qr;
            if (r > MROWS - 1) r = MROWS - 1;
            aptr[rt * 2 + rh] = A + r * DIN + qk;
        }

    float acc[2][8][4];
#pragma unroll
    for (int rt = 0; rt < 2; ++rt)
#pragma unroll
        for (int t = 0; t < 8; ++t)
#pragma unroll
            for (int e = 0; e < 4; ++e) acc[rt][t][e] = 0.f;

    float2 cur[4][2], nxt[4][2];
#pragma unroll
    for (int p = 0; p < 4; ++p) {
        cur[p][0] = *(const float2*)(aptr[p]);
        cur[p][1] = *(const float2*)(aptr[p] + 8);
    }

#pragma unroll 1
    for (int s = 0; s < 32; ++s) {
        if (s < 31) {
#pragma unroll
            for (int p = 0; p < 4; ++p) {
                nxt[p][0] = *(const float2*)(aptr[p] + (s + 1) * 16);
                nxt[p][1] = *(const float2*)(aptr[p] + (s + 1) * 16 + 8);
            }
        }
        // convert A fragments (hi + lo)
        uint32_t ah[2][4], al[2][4];
#pragma unroll
        for (int rt = 0; rt < 2; ++rt) {
            cvt_hilo(cur[2*rt][0].x,   cur[2*rt][0].y,   ah[rt][0], al[rt][0]);
            cvt_hilo(cur[2*rt+1][0].x, cur[2*rt+1][0].y, ah[rt][1], al[rt][1]);
            cvt_hilo(cur[2*rt][1].x,   cur[2*rt][1].y,   ah[rt][2], al[rt][2]);
            cvt_hilo(cur[2*rt+1][1].x, cur[2*rt+1][1].y, ah[rt][3], al[rt][3]);
        }
        // B fragments from smem + 3-product MMA
#pragma unroll
        for (int t = 0; t < 8; ++t) {
            uint4 wb = Wsm[(s * 8 + t) * 32 + lane];
#pragma unroll
            for (int rt = 0; rt < 2; ++rt) {
                mma16816(acc[rt][t][0], acc[rt][t][1], acc[rt][t][2], acc[rt][t][3],
                         ah[rt][0], ah[rt][1], ah[rt][2], ah[rt][3], wb.x, wb.y);  // hi*hi
                mma16816(acc[rt][t][0], acc[rt][t][1], acc[rt][t][2], acc[rt][t][3],
                         ah[rt][0], ah[rt][1], ah[rt][2], ah[rt][3], wb.z, wb.w);  // hi*lo
                mma16816(acc[rt][t][0], acc[rt][t][1], acc[rt][t][2], acc[rt][t][3],
                         al[rt][0], al[rt][1], al[rt][2], al[rt][3], wb.x, wb.y);  // lo*hi
            }
        }
#pragma unroll
        for (int p = 0; p < 4; ++p) { cur[p][0] = nxt[p][0]; cur[p][1] = nxt[p][1]; }
    }

    // epilogue: bias + store
#pragma unroll
    for (int rt = 0; rt < 2; ++rt)
#pragma unroll
        for (int rh = 0; rh < 2; ++rh) {
            long r = rowbase + rt * 16 + rh * 8 + qr;
            if (r < MROWS) {
                float* orow = out + r * NL;
#pragma unroll
                for (int t = 0; t < 8; ++t) {
                    int c = t * 8 + qk;
                    float2 v;
                    v.x = acc[rt][t][rh * 2 + 0] + bsm[c];
                    v.y = acc[rt][t][rh * 2 + 1] + bsm[c + 1];
                    *(float2*)(orow + c) = v;
                }
            }
        }
}

// ---------------- fused tree kernel (unchanged; near fma floor) ----------------
#define E2_PITCH 257
#define TREE_SMEM_BYTES ((2048 + 32 * E2_PITCH) * 8 + 256 * 4)

__global__ __launch_bounds__(512) void tree_kernel(
    const float* __restrict__ emis, float* __restrict__ bufA,
    float* __restrict__ bufB, float* __restrict__ outg)
{
    u64* smem = (u64*)dynsm;
    u64* W2s = smem;
    u64* E2s = smem + 2048;
    float* mbuf = (float*)(smem + 2048 + 32 * E2_PITCH);

    int t = threadIdx.x;
    int b = blockIdx.x;

    for (int i = t; i < 2048; i += 512) W2s[i] = g_w2[i];
    for (int i = t; i < 32 * E2_PITCH; i += 512) E2s[i] = 0ull;
    if (t < 256) mbuf[t] = 0.f;
    __syncthreads();

    const float* emisb = emis + (size_t)b * NNODES * NL;
    const float* prev  = emisb + (size_t)(LEAVES - 1) * NL;
    float* bufAb = bufA + (size_t)b * 512 * NL;
    float* bufBb = bufB + (size_t)b * 256 * NL;

    int cvg = t & 31, lg = t >> 5;
    int sub = t & 3,  cquad = t >> 2;

    for (int d = 9; d >= 0; --d) {
        int n = 1 << d;
        const float* emisLvl = emisb + (size_t)(n - 1) * NL;
        float* outLvl = (d == 0) ? (outg + (size_t)b * NL)
                                 : ((d & 1) ? bufAb : bufBb);
        int ntiles = (n + 127) >> 7;
        for (int tile = 0; tile < ntiles; ++tile) {
            int i0 = tile << 7;
            int NT = n - i0; if (NT > 128) NT = 128;
            int ncv = 2 * NT;

#pragma unroll
            for (int co = 0; co < 256; co += 128) {
                int c = co + cquad;
                bool valid = c < ncv;
                int cc = valid ? c : 0;
                const float* src = prev + (size_t)(i0 * 2 + cc) * NL + sub * 16;
                float4 v0 = *(const float4*)(src);
                float4 v1 = *(const float4*)(src + 4);
                float4 v2 = *(const float4*)(src + 8);
                float4 v3 = *(const float4*)(src + 12);
                float vv[16] = {v0.x, v0.y, v0.z, v0.w, v1.x, v1.y, v1.z, v1.w,
                                v2.x, v2.y, v2.z, v2.w, v3.x, v3.y, v3.z, v3.w};
                float m = vv[0];
#pragma unroll
                for (int j = 1; j < 16; ++j) m = fmaxf(m, vv[j]);
                m = fmaxf(m, __shfl_xor_sync(0xffffffffu, m, 1));
                m = fmaxf(m, __shfl_xor_sync(0xffffffffu, m, 2));
                if (valid) {
#pragma unroll
                    for (int j = 0; j < 8; ++j) {
                        float e0 = __expf(vv[2 * j] - m);
                        float e1 = __expf(vv[2 * j + 1] - m);
                        E2s[(sub * 8 + j) * E2_PITCH + c] = pack2(e0, e1);
                    }
                    if (sub == 0) mbuf[c] = m;
                }
            }
            __syncthreads();

            u64 acc[8][4];
#pragma unroll
            for (int i = 0; i < 8; ++i)
#pragma unroll
                for (int j = 0; j < 4; ++j) acc[i][j] = 0ull;

#pragma unroll 2
            for (int kp = 0; kp < 32; ++kp) {
                const u64* er = E2s + kp * E2_PITCH + cvg;
                const u64* wr = W2s + kp * NL + lg;
                u64 w0 = wr[0], w1 = wr[16], w2v = wr[32], w3 = wr[48];
#pragma unroll
                for (int i = 0; i < 8; ++i) {
                    u64 e = er[32 * i];
                    acc[i][0] = fma2(e, w0,  acc[i][0]);
                    acc[i][1] = fma2(e, w1,  acc[i][1]);
                    acc[i][2] = fma2(e, w2v, acc[i][2]);
                    acc[i][3] = fma2(e, w3,  acc[i][3]);
                }
            }

            bool isLeft = (cvg & 1) == 0;
#pragma unroll
            for (int i = 0; i < 8; ++i) {
                int cv = cvg + 32 * i;
                float mv = mbuf[cv];
#pragma unroll
                for (int j = 0; j < 4; ++j) {
                    float2 u = unpack2(acc[i][j]);
                    float lse = __logf(u.x + u.y) + mv;
                    float oth = __shfl_xor_sync(0xffffffffu, lse, 1);
                    if (isLeft && cv < ncv) {
                        int node = i0 + (cv >> 1);
                        int l = lg + 16 * j;
                        outLvl[(size_t)node * NL + l] =
                            emisLvl[(size_t)node * NL + l] + lse + oth;
                    }
                }
            }
            __syncthreads();
        }
        prev = outLvl;
    }
}

// ---------------- launch ----------------
extern "C" void kernel_launch(void* const* d_in, const int* in_sizes, int n_in,
                              void* d_out, int out_size)
{
    const float* hidden = (const float*)d_in[0];
    const float* W      = (const float*)d_in[1];
    const float* bias   = (const float*)d_in[2];
    const float* trans  = (const float*)d_in[3];
    float* out = (float*)d_out;

    float *emis, *bufA, *bufB;
    cudaGetSymbolAddress((void**)&emis, g_emis);
    cudaGetSymbolAddress((void**)&bufA, g_bufA);
    cudaGetSymbolAddress((void**)&bufB, g_bufB);

    init_kernel<<<(2048 + 32 * 8 * 32 + 255) / 256, 256>>>(trans, W);

    cudaFuncSetAttribute(gemm_kernel, cudaFuncAttributeMaxDynamicSharedMemorySize, GS_TOTAL);
    gemm_kernel<<<(MROWS + 511) / 512, 512, GS_TOTAL>>>(hidden, bias, emis);

    cudaFuncSetAttribute(tree_kernel, cudaFuncAttributeMaxDynamicSharedMemorySize, TREE_SMEM_BYTES);
    tree_kernel<<<B_SZ, 512, TREE_SMEM_BYTES>>>(emis, bufA, bufB, out);
}